// round 16
// baseline (speedup 1.0000x reference)
#include <cuda_runtime.h>
#include <cuda_bf16.h>
#include <stdint.h>
#include <math.h>

#define B_ 4
#define S_ 2048
#define T_ 2048
#define C_ 256
#define BST 16777216  // B_*S_*T_
#define XN  2097152   // B_*S_*C_
#define PN  4194304   // 2*B_*S_*C_
#define NCH 128       // conf chunks per batch (16 rows each)

// ---- tcgen05 only legal when an sm_103a feature pass exists ----
#if defined(__CUDA_ARCH__) && defined(__CUDA_ARCH_FEAT_SM103_ALL)
#define HAS_TC 1
#else
#define HAS_TC 0
#endif

// ---------------- scratch (device globals; no runtime allocation) -------------
__device__ __nv_bfloat16 g_Xhi[PN];
__device__ __nv_bfloat16 g_Xlo[PN];
__device__ __nv_bfloat16 g_Whi[C_*C_];
__device__ __nv_bfloat16 g_Wlo[C_*C_];
__device__ __nv_bfloat16 g_Phi[PN];
__device__ __nv_bfloat16 g_Plo[PN];
__device__ float         g_sim[BST];   // holds exp(sim)

__device__ float g_rZrow[B_*S_], g_Rmax[B_*S_];
__device__ int   g_Ridx[B_*S_];
__device__ float g_rZcol[B_*T_], g_Cmax[B_*T_];
__device__ float g_pR[B_*16*S_];                    // row-sum partials (bn*2+half)
__device__ float g_pC[B_*16*T_];                    // col-sum partials (bm)
__device__ unsigned char g_smask[B_*S_], g_tmask[B_*T_];

// ============================ PTX helpers =====================================
__device__ __forceinline__ uint32_t smem_u32(const void* p) {
    uint32_t a;
    asm("{ .reg .u64 t; cvta.to.shared.u64 t, %1; cvt.u32.u64 %0, t; }" : "=r"(a) : "l"(p));
    return a;
}
__device__ __forceinline__ void cp16(uint32_t dst, const void* src) {
    asm volatile("cp.async.cg.shared.global [%0], [%1], 16;\n" :: "r"(dst), "l"(src));
}
#define CP_COMMIT()  asm volatile("cp.async.commit_group;\n" ::: "memory")

#if HAS_TC
#define TC_ALLOC(smem_addr, n)   asm volatile("tcgen05.alloc.cta_group::1.sync.aligned.shared::cta.b32 [%0], %1;" :: "r"(smem_addr), "r"((uint32_t)(n)) : "memory")
#define TC_DEALLOC(tmem, n)      asm volatile("tcgen05.dealloc.cta_group::1.sync.aligned.b32 %0, %1;" :: "r"(tmem), "r"((uint32_t)(n)))
#define TC_RELINQ()              asm volatile("tcgen05.relinquish_alloc_permit.cta_group::1.sync.aligned;")
#define TC_COMMIT(mbar)          asm volatile("tcgen05.commit.cta_group::1.mbarrier::arrive::one.shared::cluster.b64 [%0];" :: "r"(mbar) : "memory")
#define TC_FENCE_AFTER()         asm volatile("tcgen05.fence::after_thread_sync;" ::: "memory")
#define TC_WAIT_LD()             asm volatile("tcgen05.wait::ld.sync.aligned;" ::: "memory")
#define FENCE_ASYNC_SHARED()     asm volatile("fence.proxy.async.shared::cta;" ::: "memory")
#define MBAR_INIT(a, c)          asm volatile("mbarrier.init.shared.b64 [%0], %1;" :: "r"(a), "r"((uint32_t)(c)) : "memory")
#define MBAR_INVAL(a)            asm volatile("mbarrier.inval.shared.b64 [%0];" :: "r"(a) : "memory")

#define MBAR_WAIT(a, par) do { \
    uint32_t _m = (a), _p = (par), _d; \
    asm volatile("{\n\t.reg .pred p;\n\t" \
        "mbarrier.try_wait.parity.acquire.cta.shared::cta.b64 p, [%1], %2;\n\t" \
        "selp.b32 %0, 1, 0, p;\n\t}" : "=r"(_d) : "r"(_m), "r"(_p) : "memory"); \
    if (!_d) { \
        asm volatile("{\n\t.reg .pred P1;\n\t" \
            "WL_%=:\n\t" \
            "mbarrier.try_wait.parity.acquire.cta.shared::cta.b64 P1, [%0], %1, 0x989680;\n\t" \
            "@P1 bra.uni WD_%=;\n\t" \
            "bra.uni WL_%=;\n\t" \
            "WD_%=:\n\t}" :: "r"(_m), "r"(_p) : "memory"); \
    } \
} while (0)

#define LDTM_X32(r, addr) \
    asm volatile("tcgen05.ld.sync.aligned.32x32b.x32.b32 " \
        "{%0,%1,%2,%3,%4,%5,%6,%7,%8,%9,%10,%11,%12,%13,%14,%15," \
        "%16,%17,%18,%19,%20,%21,%22,%23,%24,%25,%26,%27,%28,%29,%30,%31}, [%32];" \
        : "=r"((r)[0]), "=r"((r)[1]), "=r"((r)[2]), "=r"((r)[3]), \
          "=r"((r)[4]), "=r"((r)[5]), "=r"((r)[6]), "=r"((r)[7]), \
          "=r"((r)[8]), "=r"((r)[9]), "=r"((r)[10]), "=r"((r)[11]), \
          "=r"((r)[12]), "=r"((r)[13]), "=r"((r)[14]), "=r"((r)[15]), \
          "=r"((r)[16]), "=r"((r)[17]), "=r"((r)[18]), "=r"((r)[19]), \
          "=r"((r)[20]), "=r"((r)[21]), "=r"((r)[22]), "=r"((r)[23]), \
          "=r"((r)[24]), "=r"((r)[25]), "=r"((r)[26]), "=r"((r)[27]), \
          "=r"((r)[28]), "=r"((r)[29]), "=r"((r)[30]), "=r"((r)[31]) \
        : "r"(addr))

__device__ __forceinline__ uint32_t elect_one() {
    uint32_t p;
    asm volatile("{\n\t.reg .pred e;\n\telect.sync _|e, 0xFFFFFFFF;\n\t"
                 "selp.b32 %0, 1, 0, e;\n\t}" : "=r"(p));
    return p;
}
__device__ __forceinline__ uint64_t mk_desc(uint32_t addr) {
    const uint64_t base =
        (uint64_t(2) << 61) | (uint64_t(1) << 46) | (uint64_t(64) << 32) | (uint64_t(1) << 16);
    return base | ((uint64_t)(addr >> 4) & 0x3FFF);
}
__device__ __forceinline__ void umma_bf16_ss(uint32_t d, uint64_t a, uint64_t b,
                                             uint32_t idesc, uint32_t en) {
    asm volatile(
        "{\n\t.reg .pred p;\n\t"
        "setp.ne.u32 p, %4, 0;\n\t"
        "tcgen05.mma.cta_group::1.kind::f16 [%0], %1, %2, %3, {%5,%5,%5,%5}, p;\n\t}"
        :: "r"(d), "l"(a), "l"(b), "r"(idesc), "r"(en), "r"(0u)
        : "memory");
}
#define SIM_IDESC128 0x8200490u
#endif  // HAS_TC

// ------------- fused prep: masks + fp32->(hi,lo) splits for src, tgt, W ----------
__global__ void k_prep(const float* __restrict__ src, const float* __restrict__ tgt,
                       const float* __restrict__ W,
                       const unsigned char* __restrict__ smk,
                       const unsigned char* __restrict__ tmk) {
    int i = blockIdx.x * blockDim.x + threadIdx.x;
    if (i < B_*S_) {
        bool ws = (smk[1] == 0);
        bool wt = (tmk[1] == 0);
        g_smask[i] = ws ? (((const int*)smk)[i] != 0) : (smk[i] != 0);
        g_tmask[i] = wt ? (((const int*)tmk)[i] != 0) : (tmk[i] != 0);
    }
    const float* x; __nv_bfloat16 *hi, *lo; int off;
    if (i < XN)            { x = src; off = i;          hi = g_Xhi;      lo = g_Xlo; }
    else if (i < 2*XN)     { x = tgt; off = i - XN;     hi = g_Xhi + XN; lo = g_Xlo + XN; }
    else if (i < 2*XN + C_*C_) { x = W; off = i - 2*XN; hi = g_Whi;      lo = g_Wlo; }
    else return;
    float v = x[off];
    __nv_bfloat16 h = __float2bfloat16(v);
    hi[off] = h;
    lo[off] = __float2bfloat16(v - __bfloat162float(h));
}

// ============ tcgen05 GEMM: resident A + 2 interleaved N=128 tiles =================
// MODE 0 (sim): out = exp(D*scale); epilogue also emits row/col denominator partials.
// MODE 1 (proj): out = split(D*scale).
// Pipeline: slack-3 (wait commit(c-3)), 3 mbarriers (k%3, phase (k/3)&1), 6 B slots.
#define SIM_SMEM  230400
#define OFF_B     131072
#define STG_PAD   257

template<int MODE>
__global__ __launch_bounds__(256, 1)
void k_tc(const __nv_bfloat16* __restrict__ Ah_g, const __nv_bfloat16* __restrict__ Al_g,
          const __nv_bfloat16* __restrict__ Bh_g, const __nv_bfloat16* __restrict__ Bl_g,
          float* __restrict__ simout, __nv_bfloat16* __restrict__ PhO,
          __nv_bfloat16* __restrict__ PlO, float scale)
{
#if HAS_TC
    extern __shared__ char ds[];
    __shared__ uint32_t s_tptr;
    __shared__ __align__(16) uint64_t s_mbar[3];

    const int tid = threadIdx.x, lane = tid & 31, wid = tid >> 5;
    const int bn = blockIdx.x, bm = (MODE == 0) ? blockIdx.y : blockIdx.x;
    const int z  = blockIdx.z;
    const uint32_t dsb = (smem_u32(ds) + 1023u) & ~1023u;
    char* dsp = ds + (dsb - smem_u32(ds));
    uint32_t mbs[3] = { smem_u32(&s_mbar[0]), smem_u32(&s_mbar[1]), smem_u32(&s_mbar[2]) };

    const char *Ahsrc, *Alsrc, *Bhsrc, *Blsrc;
    if (MODE == 0) {
        Ahsrc = (const char*)(Ah_g + ((size_t)z * S_ + bm * 128) * C_);
        Alsrc = (const char*)(Al_g + ((size_t)z * S_ + bm * 128) * C_);
        Bhsrc = (const char*)(Bh_g + ((size_t)z * T_ + bn * 256) * C_);
        Blsrc = (const char*)(Bl_g + ((size_t)z * T_ + bn * 256) * C_);
    } else {
        Ahsrc = (const char*)(Ah_g + (size_t)bm * 128 * C_);
        Alsrc = (const char*)(Al_g + (size_t)bm * 128 * C_);
        Bhsrc = (const char*)Bh_g;
        Blsrc = (const char*)Bl_g;
    }

    if (wid == 0) TC_ALLOC(smem_u32(&s_tptr), 256);
    if (tid == 0) { MBAR_INIT(mbs[0], 1); MBAR_INIT(mbs[1], 1); MBAR_INIT(mbs[2], 1); }
    __syncthreads();
    const uint32_t tmem = s_tptr;

    auto loadA = [&]() {
#pragma unroll
        for (int j = 0; j < 32; j++) {
            int c = tid + j * 256;
            int tile = c >> 10, idx = c & 1023;
            int row = idx >> 3, seg = idx & 7;
            const char* base = (tile < 4) ? Ahsrc : Alsrc;
            int kc = tile & 3;
            const char* s = base + (size_t)row * 512 + kc * 128 + seg * 16;
            uint32_t boff = (uint32_t)(row * 128 + seg * 16) ^ ((uint32_t)(row & 7) << 4);
            cp16(dsb + tile * 16384 + boff, s);
        }
        CP_COMMIT();
    };

    auto loadB = [&](int c) {
        const int tc = c & 1, q = c >> 1, kc = q & 3, slot = c % 6;
        const char* base = ((q < 4) ? Bhsrc : Blsrc) + (size_t)tc * 128 * 512;
#pragma unroll
        for (int j = 0; j < 4; j++) {
            int cx = tid + j * 256;
            int row = cx >> 3, seg = cx & 7;
            const char* s = base + (size_t)row * 512 + kc * 128 + seg * 16;
            uint32_t boff = (uint32_t)(row * 128 + seg * 16) ^ ((uint32_t)(row & 7) << 4);
            cp16(dsb + OFF_B + slot * 16384 + boff, s);
        }
        CP_COMMIT();
    };

    // prolog: B0, A, B1..B4 (6 commit groups)
    loadB(0);
    loadA();
    loadB(1); loadB(2); loadB(3); loadB(4);

#pragma unroll
    for (int c = 0; c < 16; c++) {
        if (c >= 3) {                        // wait commit(c-3): slack-3
            const int k = c - 3;
            MBAR_WAIT(mbs[k % 3], (k / 3) & 1);
        }
        if (c >= 2 && c <= 12) loadB(c + 3);
        if (c == 0)       asm volatile("cp.async.wait_group 4;\n" ::: "memory");
        else if (c <= 12) asm volatile("cp.async.wait_group 3;\n" ::: "memory");
        else if (c == 13) asm volatile("cp.async.wait_group 2;\n" ::: "memory");
        else if (c == 14) asm volatile("cp.async.wait_group 1;\n" ::: "memory");
        else              asm volatile("cp.async.wait_group 0;\n" ::: "memory");
        __syncthreads();
        if (wid == 0) {
            if (elect_one()) {
                FENCE_ASYNC_SHARED();
                const int tc = c & 1, q = c >> 1, kc = q & 3, slot = c % 6;
                uint64_t ah = mk_desc(dsb + kc * 16384);
                uint64_t al = mk_desc(dsb + 65536 + kc * 16384);
                uint64_t bd = mk_desc(dsb + OFF_B + slot * 16384);
                uint32_t D = tmem + tc * 128;
                if (q < 4) {
#pragma unroll
                    for (int ks = 0; ks < 4; ks++) {
                        umma_bf16_ss(D, ah + ks * 2, bd + ks * 2, SIM_IDESC128,
                                     (q > 0) || (ks > 0));
                        umma_bf16_ss(D, al + ks * 2, bd + ks * 2, SIM_IDESC128, 1u);
                    }
                } else {
#pragma unroll
                    for (int ks = 0; ks < 4; ks++)
                        umma_bf16_ss(D, ah + ks * 2, bd + ks * 2, SIM_IDESC128, 1u);
                }
                TC_COMMIT(mbs[c % 3]);
            }
        }
    }
    MBAR_WAIT(mbs[1], 0);   // k=13: 13%3=1, (13/3)&1=0
    MBAR_WAIT(mbs[2], 0);   // k=14: 14%3=2, (14/3)&1=0
    MBAR_WAIT(mbs[0], 1);   // k=15: 15%3=0, (15/3)&1=1

    TC_FENCE_AFTER();
    const int sub = wid & 3, half = (wid >> 2) * 128;
    if (MODE == 0) {
        float* stage  = (float*)dsp;
        float* tmaskf = stage + 128 * STG_PAD;
        float* smaskf = tmaskf + 256;
        __syncthreads();
        tmaskf[tid] = g_tmask[z * T_ + bn * 256 + tid] ? 1.f : 0.f;
        if (tid < 128) smaskf[tid] = g_smask[z * S_ + bm * 128 + tid] ? 1.f : 0.f;
        __syncthreads();

        const int row = sub * 32 + lane;
        const float smk = smaskf[row];
        float rsum = 0.f;
        float* out = simout + ((size_t)z * S_ + bm * 128 + row) * T_ + bn * 256 + half;
#pragma unroll
        for (int cb = 0; cb < 4; cb++) {
            uint32_t r[32];
            LDTM_X32(r, tmem + half + cb * 32);
            TC_WAIT_LD();
#pragma unroll
            for (int i = 0; i < 8; i++) {
                float e0 = __expf(__uint_as_float(r[i*4+0]) * scale);
                float e1 = __expf(__uint_as_float(r[i*4+1]) * scale);
                float e2 = __expf(__uint_as_float(r[i*4+2]) * scale);
                float e3 = __expf(__uint_as_float(r[i*4+3]) * scale);
                *reinterpret_cast<float4*>(out + cb * 32 + i * 4) =
                    make_float4(e0, e1, e2, e3);
                int col = half + cb * 32 + i * 4;
                rsum += e0 * tmaskf[col] + e1 * tmaskf[col + 1]
                      + e2 * tmaskf[col + 2] + e3 * tmaskf[col + 3];
                float* sp = stage + row * STG_PAD + col;
                sp[0] = e0 * smk; sp[1] = e1 * smk; sp[2] = e2 * smk; sp[3] = e3 * smk;
            }
        }
        g_pR[((z * 8 + bn) * 2 + (half >> 7)) * S_ + bm * 128 + row] = rsum;
        __syncthreads();
        float csum = 0.f;
#pragma unroll 8
        for (int rr = 0; rr < 128; rr++) csum += stage[rr * STG_PAD + tid];
        g_pC[(z * 16 + bm) * T_ + bn * 256 + tid] = csum;
    } else {
        size_t g = (size_t)(bm * 128 + sub * 32 + lane) * C_ + half;
#pragma unroll
        for (int cb = 0; cb < 4; cb++) {
            uint32_t r[32];
            LDTM_X32(r, tmem + half + cb * 32);
            TC_WAIT_LD();
#pragma unroll
            for (int i = 0; i < 8; i++) {
                float v0 = __uint_as_float(r[i*4+0]) * scale;
                float v1 = __uint_as_float(r[i*4+1]) * scale;
                float v2 = __uint_as_float(r[i*4+2]) * scale;
                float v3 = __uint_as_float(r[i*4+3]) * scale;
                __nv_bfloat16 h0 = __float2bfloat16(v0), h1 = __float2bfloat16(v1);
                __nv_bfloat16 h2 = __float2bfloat16(v2), h3 = __float2bfloat16(v3);
                __nv_bfloat162 hp01; hp01.x = h0; hp01.y = h1;
                __nv_bfloat162 hp23; hp23.x = h2; hp23.y = h3;
                __nv_bfloat162 lp01, lp23;
                lp01.x = __float2bfloat16(v0 - __bfloat162float(h0));
                lp01.y = __float2bfloat16(v1 - __bfloat162float(h1));
                lp23.x = __float2bfloat16(v2 - __bfloat162float(h2));
                lp23.y = __float2bfloat16(v3 - __bfloat162float(h3));
                size_t off = g + cb * 32 + i * 4;
                *reinterpret_cast<__nv_bfloat162*>(PhO + off)     = hp01;
                *reinterpret_cast<__nv_bfloat162*>(PhO + off + 2) = hp23;
                *reinterpret_cast<__nv_bfloat162*>(PlO + off)     = lp01;
                *reinterpret_cast<__nv_bfloat162*>(PlO + off + 2) = lp23;
            }
        }
    }

    __syncthreads();
    if (tid == 0) { MBAR_INVAL(mbs[0]); MBAR_INVAL(mbs[1]); MBAR_INVAL(mbs[2]); }
    __syncthreads();
    if (wid == 0) { TC_RELINQ(); TC_DEALLOC(tmem, 256); }
#else
    (void)Ah_g; (void)Al_g; (void)Bh_g; (void)Bl_g;
    (void)simout; (void)PhO; (void)PlO; (void)scale;
#endif
}

// ---- combine 16 partials (4 threads/output, shfl) + invert; also zero g_Cmax ------
__global__ void k_inv() {
    int j = blockIdx.x * blockDim.x + threadIdx.x;     // 0 .. 65535
    if (j < B_ * T_) g_Cmax[j] = 0.f;
    int o = j >> 2, q = (j & 3) * 4;
    float z = 0.f;
    if (o < B_ * S_) {
        int b = o >> 11, s = o & 2047;
#pragma unroll
        for (int p = 0; p < 4; p++) z += g_pR[(b * 16 + q + p) * S_ + s];
    } else {
        int oo = o - B_ * S_;
        int b = oo >> 11, t = oo & 2047;
#pragma unroll
        for (int p = 0; p < 4; p++) z += g_pC[(b * 16 + q + p) * T_ + t];
    }
    z += __shfl_xor_sync(0xffffffffu, z, 1);
    z += __shfl_xor_sync(0xffffffffu, z, 2);
    if ((j & 3) == 0) {
        if (o < B_ * S_) g_rZrow[o] = 1.f / z;
        else             g_rZcol[o - B_ * S_] = 1.f / z;
    }
}

// --- conf = e*e*rZr*rZc + zero-fill m + row (max,argmax) + col-max via atomicMax ----
__global__ __launch_bounds__(256) void k_conf(float* __restrict__ conf,
                                              float* __restrict__ mf,
                                              unsigned char* __restrict__ mb, int mode) {
    int b = blockIdx.y, ch = blockIdx.x, tid = threadIdx.x;
    int lane = tid & 31, wid = tid >> 5;
    int t0 = tid * 8;
    __shared__ float shv[16][8];
    __shared__ int   shi[16][8];
    float rzc[8], cm[8]; bool tm[8];
#pragma unroll
    for (int i = 0; i < 8; i++) {
        rzc[i] = g_rZcol[b * T_ + t0 + i];
        tm[i] = g_tmask[b * T_ + t0 + i];
        cm[i] = 0.f;
    }
    for (int r = 0; r < 16; r++) {
        int s = ch * 16 + r;
        bool sv = g_smask[b * S_ + s];
        float rZr = g_rZrow[b * S_ + s];
        size_t off = ((size_t)b * S_ + s) * T_ + t0;
        const float4* row = (const float4*)(g_sim + off);
        float4 w0 = row[0], w1 = row[1];
        float e[8] = {w0.x, w0.y, w0.z, w0.w, w1.x, w1.y, w1.z, w1.w};
        float v[8]; float rm = 0.f; int ri = t0;
#pragma unroll
        for (int i = 0; i < 8; i++) {
            float val = 0.f;
            if (sv && tm[i])
                val = e[i] * e[i] * rZr * rzc[i];
            v[i] = val;
            if (val > rm) { rm = val; ri = t0 + i; }
            cm[i] = fmaxf(cm[i], val);
        }
        float4* outp = (float4*)(conf + off);
        outp[0] = make_float4(v[0], v[1], v[2], v[3]);
        outp[1] = make_float4(v[4], v[5], v[6], v[7]);
        if (mode == 0) {
            float4* mp = (float4*)(mf + off);
            mp[0] = make_float4(0.f, 0.f, 0.f, 0.f);
            mp[1] = make_float4(0.f, 0.f, 0.f, 0.f);
        } else if (mode == 1) {
            *reinterpret_cast<uint2*>(mb + off) = make_uint2(0u, 0u);
        }
#pragma unroll
        for (int o = 16; o; o >>= 1) {
            float ov = __shfl_xor_sync(0xffffffffu, rm, o);
            int   oi = __shfl_xor_sync(0xffffffffu, ri, o);
            if (ov > rm) { rm = ov; ri = oi; }
        }
        if (lane == 0) { shv[r][wid] = rm; shi[r][wid] = ri; }
    }
    __syncthreads();
    if (tid < 16) {
        float bv = shv[tid][0]; int bi = shi[tid][0];
#pragma unroll
        for (int k = 1; k < 8; k++)
            if (shv[tid][k] > bv) { bv = shv[tid][k]; bi = shi[tid][k]; }
        int s = ch * 16 + tid;
        g_Rmax[b * S_ + s] = bv;
        g_Ridx[b * S_ + s] = bi;
    }
    // col-max partials -> atomicMax (values >= 0: uint ordering == float ordering)
#pragma unroll
    for (int i = 0; i < 8; i++)
        atomicMax((unsigned int*)&g_Cmax[b * T_ + t0 + i], __float_as_uint(cm[i]));
}

// ---------------- m = mutual-max mask: sparse scatter (zeros already written) ------
__global__ void k_mscatter(float* __restrict__ mf, unsigned char* __restrict__ mb,
                           int mode) {
    int i = blockIdx.x * blockDim.x + threadIdx.x;
    if (i >= B_ * S_) return;
    int b = i >> 11;
    float v = g_Rmax[i];
    int t = g_Ridx[i];
    if (v > 0.2f && v == g_Cmax[b * T_ + t]) {
        size_t off = (size_t)i * T_ + t;
        if (mode == 0) mf[off] = 1.f;
        else           mb[off] = 1;
    }
}

// ---------------- launch -------------------------------------------------------------
extern "C" void kernel_launch(void* const* d_in, const int* in_sizes, int n_in,
                              void* d_out, int out_size) {
    const float *src = nullptr, *tgt = nullptr, *W = nullptr;
    const unsigned char *smk = nullptr, *tmk = nullptr;
    for (int i = 0; i < n_in; i++) {
        if (in_sizes[i] == XN)        { if (!src) src = (const float*)d_in[i]; else tgt = (const float*)d_in[i]; }
        else if (in_sizes[i] == 8192) { if (!smk) smk = (const unsigned char*)d_in[i]; else tmk = (const unsigned char*)d_in[i]; }
        else if (in_sizes[i] == 65536) W = (const float*)d_in[i];
    }

    void *xhi, *xlo, *whi, *wlo, *phi, *plo, *sim;
    cudaGetSymbolAddress(&xhi, g_Xhi);  cudaGetSymbolAddress(&xlo, g_Xlo);
    cudaGetSymbolAddress(&whi, g_Whi);  cudaGetSymbolAddress(&wlo, g_Wlo);
    cudaGetSymbolAddress(&phi, g_Phi);  cudaGetSymbolAddress(&plo, g_Plo);
    cudaGetSymbolAddress(&sim, g_sim);

    __nv_bfloat16* Xhi = (__nv_bfloat16*)xhi;  __nv_bfloat16* Xlo = (__nv_bfloat16*)xlo;
    __nv_bfloat16* Whi = (__nv_bfloat16*)whi;  __nv_bfloat16* Wlo = (__nv_bfloat16*)wlo;
    __nv_bfloat16* Phi = (__nv_bfloat16*)phi;  __nv_bfloat16* Plo = (__nv_bfloat16*)plo;
    float* SIM = (float*)sim;

    cudaFuncSetAttribute(k_tc<0>, cudaFuncAttributeMaxDynamicSharedMemorySize, SIM_SMEM);
    cudaFuncSetAttribute(k_tc<1>, cudaFuncAttributeMaxDynamicSharedMemorySize, SIM_SMEM);

    float* conf = (float*)d_out;
    long long twoBST = 2LL * BST;
    int mode;
    if ((long long)out_size >= twoBST)             mode = 0;
    else if ((long long)out_size == BST + BST / 4) mode = 1;
    else                                           mode = 2;
    float* mf = conf + BST;
    unsigned char* mb = (unsigned char*)d_out + (size_t)BST * 4;

    // launch idx: 0 prep, 1 proj_tc, 2 sim_tc, 3 inv(+Cmax zero), 4 conf, 5 scatter
    k_prep<<<(2*XN + C_*C_ + 255) / 256, 256>>>(src, tgt, W, smk, tmk);
    k_tc<1><<<dim3(128, 1, 1), 256, SIM_SMEM>>>(
        Xhi, Xlo, Whi, Wlo, nullptr, Phi, Plo, 0.0625f);
    k_tc<0><<<dim3(8, 16, 4), 256, SIM_SMEM>>>(
        Phi, Plo, Phi + XN, Plo + XN, SIM, nullptr, nullptr, 10.f);
    k_inv<<<256, 256>>>();
    k_conf<<<dim3(NCH, B_), 256>>>(conf, mf, mb, mode);
    if (mode != 2)
        k_mscatter<<<(B_*S_ + 255) / 256, 256>>>(mf, mb, mode);
}

// round 17
// speedup vs baseline: 1.0025x; 1.0025x over previous
#include <cuda_runtime.h>
#include <cuda_bf16.h>
#include <stdint.h>
#include <math.h>

#define B_ 4
#define S_ 2048
#define T_ 2048
#define C_ 256
#define BST 16777216  // B_*S_*T_
#define XN  2097152   // B_*S_*C_
#define PN  4194304   // 2*B_*S_*C_
#define NCH 128       // conf chunks per batch (16 rows each)

// ---- tcgen05 only legal when an sm_103a feature pass exists ----
#if defined(__CUDA_ARCH__) && defined(__CUDA_ARCH_FEAT_SM103_ALL)
#define HAS_TC 1
#else
#define HAS_TC 0
#endif

// ---------------- scratch (device globals; no runtime allocation) -------------
__device__ __nv_bfloat16 g_Xhi[PN];
__device__ __nv_bfloat16 g_Xlo[PN];
__device__ __nv_bfloat16 g_Whi[C_*C_];
__device__ __nv_bfloat16 g_Wlo[C_*C_];
__device__ __nv_bfloat16 g_Phi[PN];
__device__ __nv_bfloat16 g_Plo[PN];
__device__ float         g_sim[BST];   // holds exp(sim)

__device__ float g_rZrow[B_*S_], g_Rmax[B_*S_];
__device__ int   g_Ridx[B_*S_];
__device__ float g_rZcol[B_*T_], g_Cmax[B_*T_];
__device__ float g_pR[B_*16*S_];                    // row-sum partials (bn*2+half)
__device__ float g_pC[B_*16*T_];                    // col-sum partials (bm)
__device__ unsigned char g_smask[B_*S_], g_tmask[B_*T_];

// ============================ PTX helpers =====================================
__device__ __forceinline__ uint32_t smem_u32(const void* p) {
    uint32_t a;
    asm("{ .reg .u64 t; cvta.to.shared.u64 t, %1; cvt.u32.u64 %0, t; }" : "=r"(a) : "l"(p));
    return a;
}
__device__ __forceinline__ void cp16(uint32_t dst, const void* src) {
    asm volatile("cp.async.cg.shared.global [%0], [%1], 16;\n" :: "r"(dst), "l"(src));
}
#define CP_COMMIT()  asm volatile("cp.async.commit_group;\n" ::: "memory")

#if HAS_TC
#define TC_ALLOC(smem_addr, n)   asm volatile("tcgen05.alloc.cta_group::1.sync.aligned.shared::cta.b32 [%0], %1;" :: "r"(smem_addr), "r"((uint32_t)(n)) : "memory")
#define TC_DEALLOC(tmem, n)      asm volatile("tcgen05.dealloc.cta_group::1.sync.aligned.b32 %0, %1;" :: "r"(tmem), "r"((uint32_t)(n)))
#define TC_RELINQ()              asm volatile("tcgen05.relinquish_alloc_permit.cta_group::1.sync.aligned;")
#define TC_COMMIT(mbar)          asm volatile("tcgen05.commit.cta_group::1.mbarrier::arrive::one.shared::cluster.b64 [%0];" :: "r"(mbar) : "memory")
#define TC_FENCE_AFTER()         asm volatile("tcgen05.fence::after_thread_sync;" ::: "memory")
#define TC_WAIT_LD()             asm volatile("tcgen05.wait::ld.sync.aligned;" ::: "memory")
#define FENCE_ASYNC_SHARED()     asm volatile("fence.proxy.async.shared::cta;" ::: "memory")
#define MBAR_INIT(a, c)          asm volatile("mbarrier.init.shared.b64 [%0], %1;" :: "r"(a), "r"((uint32_t)(c)) : "memory")
#define MBAR_INVAL(a)            asm volatile("mbarrier.inval.shared.b64 [%0];" :: "r"(a) : "memory")

#define MBAR_WAIT(a, par) do { \
    uint32_t _m = (a), _p = (par), _d; \
    asm volatile("{\n\t.reg .pred p;\n\t" \
        "mbarrier.try_wait.parity.acquire.cta.shared::cta.b64 p, [%1], %2;\n\t" \
        "selp.b32 %0, 1, 0, p;\n\t}" : "=r"(_d) : "r"(_m), "r"(_p) : "memory"); \
    if (!_d) { \
        asm volatile("{\n\t.reg .pred P1;\n\t" \
            "WL_%=:\n\t" \
            "mbarrier.try_wait.parity.acquire.cta.shared::cta.b64 P1, [%0], %1, 0x989680;\n\t" \
            "@P1 bra.uni WD_%=;\n\t" \
            "bra.uni WL_%=;\n\t" \
            "WD_%=:\n\t}" :: "r"(_m), "r"(_p) : "memory"); \
    } \
} while (0)

#define LDTM_X32(r, addr) \
    asm volatile("tcgen05.ld.sync.aligned.32x32b.x32.b32 " \
        "{%0,%1,%2,%3,%4,%5,%6,%7,%8,%9,%10,%11,%12,%13,%14,%15," \
        "%16,%17,%18,%19,%20,%21,%22,%23,%24,%25,%26,%27,%28,%29,%30,%31}, [%32];" \
        : "=r"((r)[0]), "=r"((r)[1]), "=r"((r)[2]), "=r"((r)[3]), \
          "=r"((r)[4]), "=r"((r)[5]), "=r"((r)[6]), "=r"((r)[7]), \
          "=r"((r)[8]), "=r"((r)[9]), "=r"((r)[10]), "=r"((r)[11]), \
          "=r"((r)[12]), "=r"((r)[13]), "=r"((r)[14]), "=r"((r)[15]), \
          "=r"((r)[16]), "=r"((r)[17]), "=r"((r)[18]), "=r"((r)[19]), \
          "=r"((r)[20]), "=r"((r)[21]), "=r"((r)[22]), "=r"((r)[23]), \
          "=r"((r)[24]), "=r"((r)[25]), "=r"((r)[26]), "=r"((r)[27]), \
          "=r"((r)[28]), "=r"((r)[29]), "=r"((r)[30]), "=r"((r)[31]) \
        : "r"(addr))

__device__ __forceinline__ uint32_t elect_one() {
    uint32_t p;
    asm volatile("{\n\t.reg .pred e;\n\telect.sync _|e, 0xFFFFFFFF;\n\t"
                 "selp.b32 %0, 1, 0, e;\n\t}" : "=r"(p));
    return p;
}
__device__ __forceinline__ uint64_t mk_desc(uint32_t addr) {
    const uint64_t base =
        (uint64_t(2) << 61) | (uint64_t(1) << 46) | (uint64_t(64) << 32) | (uint64_t(1) << 16);
    return base | ((uint64_t)(addr >> 4) & 0x3FFF);
}
__device__ __forceinline__ void umma_bf16_ss(uint32_t d, uint64_t a, uint64_t b,
                                             uint32_t idesc, uint32_t en) {
    asm volatile(
        "{\n\t.reg .pred p;\n\t"
        "setp.ne.u32 p, %4, 0;\n\t"
        "tcgen05.mma.cta_group::1.kind::f16 [%0], %1, %2, %3, {%5,%5,%5,%5}, p;\n\t}"
        :: "r"(d), "l"(a), "l"(b), "r"(idesc), "r"(en), "r"(0u)
        : "memory");
}
#define SIM_IDESC128 0x8200490u
#endif  // HAS_TC

// ------------- fused prep: masks + fp32->(hi,lo) splits for src, tgt, W ----------
__global__ void k_prep(const float* __restrict__ src, const float* __restrict__ tgt,
                       const float* __restrict__ W,
                       const unsigned char* __restrict__ smk,
                       const unsigned char* __restrict__ tmk) {
    int i = blockIdx.x * blockDim.x + threadIdx.x;
    if (i < B_*S_) {
        bool ws = (smk[1] == 0);
        bool wt = (tmk[1] == 0);
        g_smask[i] = ws ? (((const int*)smk)[i] != 0) : (smk[i] != 0);
        g_tmask[i] = wt ? (((const int*)tmk)[i] != 0) : (tmk[i] != 0);
    }
    const float* x; __nv_bfloat16 *hi, *lo; int off;
    if (i < XN)            { x = src; off = i;          hi = g_Xhi;      lo = g_Xlo; }
    else if (i < 2*XN)     { x = tgt; off = i - XN;     hi = g_Xhi + XN; lo = g_Xlo + XN; }
    else if (i < 2*XN + C_*C_) { x = W; off = i - 2*XN; hi = g_Whi;      lo = g_Wlo; }
    else return;
    float v = x[off];
    __nv_bfloat16 h = __float2bfloat16(v);
    hi[off] = h;
    lo[off] = __float2bfloat16(v - __bfloat162float(h));
}

// ============ tcgen05 GEMM: resident A + 2 interleaved N=128 tiles =================
// MODE 0 (sim): out = exp(D*scale); epilogue also emits row/col denominator partials.
// MODE 1 (proj): out = split(D*scale).
// Pipeline: slack-2 (wait commit(c-2)), 2 mbarriers, 6 B slots, prefetch depth 4.
#define SIM_SMEM  230400
#define OFF_B     131072
#define STG_PAD   257

template<int MODE>
__global__ __launch_bounds__(256, 1)
void k_tc(const __nv_bfloat16* __restrict__ Ah_g, const __nv_bfloat16* __restrict__ Al_g,
          const __nv_bfloat16* __restrict__ Bh_g, const __nv_bfloat16* __restrict__ Bl_g,
          float* __restrict__ simout, __nv_bfloat16* __restrict__ PhO,
          __nv_bfloat16* __restrict__ PlO, float scale)
{
#if HAS_TC
    extern __shared__ char ds[];
    __shared__ uint32_t s_tptr;
    __shared__ __align__(16) uint64_t s_mbar[2];

    const int tid = threadIdx.x, lane = tid & 31, wid = tid >> 5;
    const int bn = blockIdx.x, bm = (MODE == 0) ? blockIdx.y : blockIdx.x;
    const int z  = blockIdx.z;
    const uint32_t dsb = (smem_u32(ds) + 1023u) & ~1023u;
    char* dsp = ds + (dsb - smem_u32(ds));
    const uint32_t mb0 = smem_u32(&s_mbar[0]);
    const uint32_t mb1 = smem_u32(&s_mbar[1]);

    const char *Ahsrc, *Alsrc, *Bhsrc, *Blsrc;
    if (MODE == 0) {
        Ahsrc = (const char*)(Ah_g + ((size_t)z * S_ + bm * 128) * C_);
        Alsrc = (const char*)(Al_g + ((size_t)z * S_ + bm * 128) * C_);
        Bhsrc = (const char*)(Bh_g + ((size_t)z * T_ + bn * 256) * C_);
        Blsrc = (const char*)(Bl_g + ((size_t)z * T_ + bn * 256) * C_);
    } else {
        Ahsrc = (const char*)(Ah_g + (size_t)bm * 128 * C_);
        Alsrc = (const char*)(Al_g + (size_t)bm * 128 * C_);
        Bhsrc = (const char*)Bh_g;
        Blsrc = (const char*)Bl_g;
    }

    if (wid == 0) TC_ALLOC(smem_u32(&s_tptr), 256);
    if (tid == 0) { MBAR_INIT(mb0, 1); MBAR_INIT(mb1, 1); }
    __syncthreads();
    const uint32_t tmem = s_tptr;

    auto loadA = [&]() {
#pragma unroll
        for (int j = 0; j < 32; j++) {
            int c = tid + j * 256;
            int tile = c >> 10, idx = c & 1023;
            int row = idx >> 3, seg = idx & 7;
            const char* base = (tile < 4) ? Ahsrc : Alsrc;
            int kc = tile & 3;
            const char* s = base + (size_t)row * 512 + kc * 128 + seg * 16;
            uint32_t boff = (uint32_t)(row * 128 + seg * 16) ^ ((uint32_t)(row & 7) << 4);
            cp16(dsb + tile * 16384 + boff, s);
        }
        CP_COMMIT();
    };

    auto loadB = [&](int c) {
        const int tc = c & 1, q = c >> 1, kc = q & 3, slot = c % 6;
        const char* base = ((q < 4) ? Bhsrc : Blsrc) + (size_t)tc * 128 * 512;
#pragma unroll
        for (int j = 0; j < 4; j++) {
            int cx = tid + j * 256;
            int row = cx >> 3, seg = cx & 7;
            const char* s = base + (size_t)row * 512 + kc * 128 + seg * 16;
            uint32_t boff = (uint32_t)(row * 128 + seg * 16) ^ ((uint32_t)(row & 7) << 4);
            cp16(dsb + OFF_B + slot * 16384 + boff, s);
        }
        CP_COMMIT();
    };

    // prolog: B0, A, B1..B5 (7 commit groups)
    loadB(0);
    loadA();
    loadB(1); loadB(2); loadB(3); loadB(4); loadB(5);

#pragma unroll
    for (int c = 0; c < 16; c++) {
        if (c >= 2) {                        // wait commit(c-2): slack-2
            const int k = c - 2;
            MBAR_WAIT((k & 1) ? mb1 : mb0, (k >> 1) & 1);
        }
        if (c >= 2 && c <= 11) loadB(c + 4);
        if (c == 0)       asm volatile("cp.async.wait_group 5;\n" ::: "memory");
        else if (c <= 11) asm volatile("cp.async.wait_group 4;\n" ::: "memory");
        else if (c == 12) asm volatile("cp.async.wait_group 3;\n" ::: "memory");
        else if (c == 13) asm volatile("cp.async.wait_group 2;\n" ::: "memory");
        else if (c == 14) asm volatile("cp.async.wait_group 1;\n" ::: "memory");
        else              asm volatile("cp.async.wait_group 0;\n" ::: "memory");
        __syncthreads();
        if (wid == 0) {
            if (elect_one()) {
                FENCE_ASYNC_SHARED();
                const int tc = c & 1, q = c >> 1, kc = q & 3, slot = c % 6;
                uint64_t ah = mk_desc(dsb + kc * 16384);
                uint64_t al = mk_desc(dsb + 65536 + kc * 16384);
                uint64_t bd = mk_desc(dsb + OFF_B + slot * 16384);
                uint32_t D = tmem + tc * 128;
                if (q < 4) {
#pragma unroll
                    for (int ks = 0; ks < 4; ks++) {
                        umma_bf16_ss(D, ah + ks * 2, bd + ks * 2, SIM_IDESC128,
                                     (q > 0) || (ks > 0));
                        umma_bf16_ss(D, al + ks * 2, bd + ks * 2, SIM_IDESC128, 1u);
                    }
                } else {
#pragma unroll
                    for (int ks = 0; ks < 4; ks++)
                        umma_bf16_ss(D, ah + ks * 2, bd + ks * 2, SIM_IDESC128, 1u);
                }
                TC_COMMIT((c & 1) ? mb1 : mb0);
            }
        }
    }
    MBAR_WAIT(mb0, 1);   // commit 14
    MBAR_WAIT(mb1, 1);   // commit 15

    TC_FENCE_AFTER();
    const int sub = wid & 3, half = (wid >> 2) * 128;
    if (MODE == 0) {
        float* stage  = (float*)dsp;
        float* tmaskf = stage + 128 * STG_PAD;
        float* smaskf = tmaskf + 256;
        __syncthreads();
        tmaskf[tid] = g_tmask[z * T_ + bn * 256 + tid] ? 1.f : 0.f;
        if (tid < 128) smaskf[tid] = g_smask[z * S_ + bm * 128 + tid] ? 1.f : 0.f;
        __syncthreads();

        const int row = sub * 32 + lane;
        const float smk = smaskf[row];
        float rsum = 0.f;
        float* out = simout + ((size_t)z * S_ + bm * 128 + row) * T_ + bn * 256 + half;
#pragma unroll
        for (int cb = 0; cb < 4; cb++) {
            uint32_t r[32];
            LDTM_X32(r, tmem + half + cb * 32);
            TC_WAIT_LD();
#pragma unroll
            for (int i = 0; i < 8; i++) {
                float e0 = __expf(__uint_as_float(r[i*4+0]) * scale);
                float e1 = __expf(__uint_as_float(r[i*4+1]) * scale);
                float e2 = __expf(__uint_as_float(r[i*4+2]) * scale);
                float e3 = __expf(__uint_as_float(r[i*4+3]) * scale);
                *reinterpret_cast<float4*>(out + cb * 32 + i * 4) =
                    make_float4(e0, e1, e2, e3);
                int col = half + cb * 32 + i * 4;
                rsum += e0 * tmaskf[col] + e1 * tmaskf[col + 1]
                      + e2 * tmaskf[col + 2] + e3 * tmaskf[col + 3];
                float* sp = stage + row * STG_PAD + col;
                sp[0] = e0 * smk; sp[1] = e1 * smk; sp[2] = e2 * smk; sp[3] = e3 * smk;
            }
        }
        g_pR[((z * 8 + bn) * 2 + (half >> 7)) * S_ + bm * 128 + row] = rsum;
        __syncthreads();
        float csum = 0.f;
#pragma unroll 8
        for (int rr = 0; rr < 128; rr++) csum += stage[rr * STG_PAD + tid];
        g_pC[(z * 16 + bm) * T_ + bn * 256 + tid] = csum;
    } else {
        size_t g = (size_t)(bm * 128 + sub * 32 + lane) * C_ + half;
#pragma unroll
        for (int cb = 0; cb < 4; cb++) {
            uint32_t r[32];
            LDTM_X32(r, tmem + half + cb * 32);
            TC_WAIT_LD();
#pragma unroll
            for (int i = 0; i < 8; i++) {
                float v0 = __uint_as_float(r[i*4+0]) * scale;
                float v1 = __uint_as_float(r[i*4+1]) * scale;
                float v2 = __uint_as_float(r[i*4+2]) * scale;
                float v3 = __uint_as_float(r[i*4+3]) * scale;
                __nv_bfloat16 h0 = __float2bfloat16(v0), h1 = __float2bfloat16(v1);
                __nv_bfloat16 h2 = __float2bfloat16(v2), h3 = __float2bfloat16(v3);
                __nv_bfloat162 hp01; hp01.x = h0; hp01.y = h1;
                __nv_bfloat162 hp23; hp23.x = h2; hp23.y = h3;
                __nv_bfloat162 lp01, lp23;
                lp01.x = __float2bfloat16(v0 - __bfloat162float(h0));
                lp01.y = __float2bfloat16(v1 - __bfloat162float(h1));
                lp23.x = __float2bfloat16(v2 - __bfloat162float(h2));
                lp23.y = __float2bfloat16(v3 - __bfloat162float(h3));
                size_t off = g + cb * 32 + i * 4;
                *reinterpret_cast<__nv_bfloat162*>(PhO + off)     = hp01;
                *reinterpret_cast<__nv_bfloat162*>(PhO + off + 2) = hp23;
                *reinterpret_cast<__nv_bfloat162*>(PlO + off)     = lp01;
                *reinterpret_cast<__nv_bfloat162*>(PlO + off + 2) = lp23;
            }
        }
    }

    __syncthreads();
    if (tid == 0) { MBAR_INVAL(mb0); MBAR_INVAL(mb1); }
    __syncthreads();
    if (wid == 0) { TC_RELINQ(); TC_DEALLOC(tmem, 256); }
#else
    (void)Ah_g; (void)Al_g; (void)Bh_g; (void)Bl_g;
    (void)simout; (void)PhO; (void)PlO; (void)scale;
#endif
}

// ---- combine 16 partials (4 threads/output, shfl) + invert; also zero g_Cmax ------
__global__ void k_inv() {
    int j = blockIdx.x * blockDim.x + threadIdx.x;     // 0 .. 65535
    if (j < B_ * T_) g_Cmax[j] = 0.f;
    int o = j >> 2, q = (j & 3) * 4;
    float z = 0.f;
    if (o < B_ * S_) {
        int b = o >> 11, s = o & 2047;
#pragma unroll
        for (int p = 0; p < 4; p++) z += g_pR[(b * 16 + q + p) * S_ + s];
    } else {
        int oo = o - B_ * S_;
        int b = oo >> 11, t = oo & 2047;
#pragma unroll
        for (int p = 0; p < 4; p++) z += g_pC[(b * 16 + q + p) * T_ + t];
    }
    z += __shfl_xor_sync(0xffffffffu, z, 1);
    z += __shfl_xor_sync(0xffffffffu, z, 2);
    if ((j & 3) == 0) {
        if (o < B_ * S_) g_rZrow[o] = 1.f / z;
        else             g_rZcol[o - B_ * S_] = 1.f / z;
    }
}

// --- conf = e*e*rZr*rZc + zero-fill m + row (max,argmax) + col-max via atomicMax ----
__global__ __launch_bounds__(256) void k_conf(float* __restrict__ conf,
                                              float* __restrict__ mf,
                                              unsigned char* __restrict__ mb, int mode) {
    int b = blockIdx.y, ch = blockIdx.x, tid = threadIdx.x;
    int lane = tid & 31, wid = tid >> 5;
    int t0 = tid * 8;
    __shared__ float shv[16][8];
    __shared__ int   shi[16][8];
    float rzc[8], cm[8]; bool tm[8];
#pragma unroll
    for (int i = 0; i < 8; i++) {
        rzc[i] = g_rZcol[b * T_ + t0 + i];
        tm[i] = g_tmask[b * T_ + t0 + i];
        cm[i] = 0.f;
    }
    for (int r = 0; r < 16; r++) {
        int s = ch * 16 + r;
        bool sv = g_smask[b * S_ + s];
        float rZr = g_rZrow[b * S_ + s];
        size_t off = ((size_t)b * S_ + s) * T_ + t0;
        const float4* row = (const float4*)(g_sim + off);
        float4 w0 = row[0], w1 = row[1];
        float e[8] = {w0.x, w0.y, w0.z, w0.w, w1.x, w1.y, w1.z, w1.w};
        float v[8]; float rm = 0.f; int ri = t0;
#pragma unroll
        for (int i = 0; i < 8; i++) {
            float val = 0.f;
            if (sv && tm[i])
                val = e[i] * e[i] * rZr * rzc[i];
            v[i] = val;
            if (val > rm) { rm = val; ri = t0 + i; }
            cm[i] = fmaxf(cm[i], val);
        }
        float4* outp = (float4*)(conf + off);
        outp[0] = make_float4(v[0], v[1], v[2], v[3]);
        outp[1] = make_float4(v[4], v[5], v[6], v[7]);
        if (mode == 0) {
            float4* mp = (float4*)(mf + off);
            mp[0] = make_float4(0.f, 0.f, 0.f, 0.f);
            mp[1] = make_float4(0.f, 0.f, 0.f, 0.f);
        } else if (mode == 1) {
            *reinterpret_cast<uint2*>(mb + off) = make_uint2(0u, 0u);
        }
#pragma unroll
        for (int o = 16; o; o >>= 1) {
            float ov = __shfl_xor_sync(0xffffffffu, rm, o);
            int   oi = __shfl_xor_sync(0xffffffffu, ri, o);
            if (ov > rm) { rm = ov; ri = oi; }
        }
        if (lane == 0) { shv[r][wid] = rm; shi[r][wid] = ri; }
    }
    __syncthreads();
    if (tid < 16) {
        float bv = shv[tid][0]; int bi = shi[tid][0];
#pragma unroll
        for (int k = 1; k < 8; k++)
            if (shv[tid][k] > bv) { bv = shv[tid][k]; bi = shi[tid][k]; }
        int s = ch * 16 + tid;
        g_Rmax[b * S_ + s] = bv;
        g_Ridx[b * S_ + s] = bi;
    }
    // col-max partials -> atomicMax (values >= 0: uint ordering == float ordering)
#pragma unroll
    for (int i = 0; i < 8; i++)
        atomicMax((unsigned int*)&g_Cmax[b * T_ + t0 + i], __float_as_uint(cm[i]));
}

// ---------------- m = mutual-max mask: sparse scatter (zeros already written) ------
__global__ void k_mscatter(float* __restrict__ mf, unsigned char* __restrict__ mb,
                           int mode) {
    int i = blockIdx.x * blockDim.x + threadIdx.x;
    if (i >= B_ * S_) return;
    int b = i >> 11;
    float v = g_Rmax[i];
    int t = g_Ridx[i];
    if (v > 0.2f && v == g_Cmax[b * T_ + t]) {
        size_t off = (size_t)i * T_ + t;
        if (mode == 0) mf[off] = 1.f;
        else           mb[off] = 1;
    }
}

// ---------------- launch -------------------------------------------------------------
extern "C" void kernel_launch(void* const* d_in, const int* in_sizes, int n_in,
                              void* d_out, int out_size) {
    const float *src = nullptr, *tgt = nullptr, *W = nullptr;
    const unsigned char *smk = nullptr, *tmk = nullptr;
    for (int i = 0; i < n_in; i++) {
        if (in_sizes[i] == XN)        { if (!src) src = (const float*)d_in[i]; else tgt = (const float*)d_in[i]; }
        else if (in_sizes[i] == 8192) { if (!smk) smk = (const unsigned char*)d_in[i]; else tmk = (const unsigned char*)d_in[i]; }
        else if (in_sizes[i] == 65536) W = (const float*)d_in[i];
    }

    void *xhi, *xlo, *whi, *wlo, *phi, *plo, *sim;
    cudaGetSymbolAddress(&xhi, g_Xhi);  cudaGetSymbolAddress(&xlo, g_Xlo);
    cudaGetSymbolAddress(&whi, g_Whi);  cudaGetSymbolAddress(&wlo, g_Wlo);
    cudaGetSymbolAddress(&phi, g_Phi);  cudaGetSymbolAddress(&plo, g_Plo);
    cudaGetSymbolAddress(&sim, g_sim);

    __nv_bfloat16* Xhi = (__nv_bfloat16*)xhi;  __nv_bfloat16* Xlo = (__nv_bfloat16*)xlo;
    __nv_bfloat16* Whi = (__nv_bfloat16*)whi;  __nv_bfloat16* Wlo = (__nv_bfloat16*)wlo;
    __nv_bfloat16* Phi = (__nv_bfloat16*)phi;  __nv_bfloat16* Plo = (__nv_bfloat16*)plo;
    float* SIM = (float*)sim;

    cudaFuncSetAttribute(k_tc<0>, cudaFuncAttributeMaxDynamicSharedMemorySize, SIM_SMEM);
    cudaFuncSetAttribute(k_tc<1>, cudaFuncAttributeMaxDynamicSharedMemorySize, SIM_SMEM);

    float* conf = (float*)d_out;
    long long twoBST = 2LL * BST;
    int mode;
    if ((long long)out_size >= twoBST)             mode = 0;
    else if ((long long)out_size == BST + BST / 4) mode = 1;
    else                                           mode = 2;
    float* mf = conf + BST;
    unsigned char* mb = (unsigned char*)d_out + (size_t)BST * 4;

    // launch idx: 0 prep, 1 proj_tc, 2 sim_tc, 3 inv(+Cmax zero), 4 conf, 5 scatter
    k_prep<<<(2*XN + C_*C_ + 255) / 256, 256>>>(src, tgt, W, smk, tmk);
    k_tc<1><<<dim3(128, 1, 1), 256, SIM_SMEM>>>(
        Xhi, Xlo, Whi, Wlo, nullptr, Phi, Plo, 0.0625f);
    k_tc<0><<<dim3(8, 16, 4), 256, SIM_SMEM>>>(
        Phi, Plo, Phi + XN, Plo + XN, SIM, nullptr, nullptr, 10.f);
    k_inv<<<256, 256>>>();
    k_conf<<<dim3(NCH, B_), 256>>>(conf, mf, mb, mode);
    if (mode != 2)
        k_mscatter<<<(B_*S_ + 255) / 256, 256>>>(mf, mb, mode);
}